// round 2
// baseline (speedup 1.0000x reference)
#include <cuda_runtime.h>

#define NF 128
#define MAXN 100000

// ---- scratch (device globals: no allocation allowed) ----
__device__ float g_deg[MAXN];
__device__ float g_dis[MAXN];
__device__ float g_h[(size_t)MAXN * NF];
__device__ float g_agg[(size_t)MAXN * NF];
__device__ float g_sum[NF];
__device__ float g_sumsq[NF];
__device__ float g_shift[NF];
__device__ float g_scale[NF];
__device__ float g_beta[NF];

// ---- vector reduction: red.global.add.v4.f32 (sm_90+) ----
__device__ __forceinline__ void red_add_v4(float* p, float4 v) {
    asm volatile("red.global.add.v4.f32 [%0], {%1, %2, %3, %4};"
                 :: "l"(p), "f"(v.x), "f"(v.y), "f"(v.z), "f"(v.w)
                 : "memory");
}

// ---- init: deg = 1 (self loop), zero stats ----
__global__ void k_init(int n) {
    int i = blockIdx.x * blockDim.x + threadIdx.x;
    if (i < NF) { g_sum[i] = 0.f; g_sumsq[i] = 0.f; }
    if (i < n) g_deg[i] = 1.0f;
}

// ---- degree count over dst (edge_index is int32) ----
__global__ void k_deg(const int* __restrict__ ei, int E) {
    int i = blockIdx.x * blockDim.x + threadIdx.x;
    if (i < E) atomicAdd(&g_deg[ei[E + i]], 1.0f);
}

__global__ void k_dis(int n) {
    int i = blockIdx.x * blockDim.x + threadIdx.x;
    if (i < n) g_dis[i] = rsqrtf(g_deg[i]);
}

// ---- GEMM: h = x @ W. 128x128 tile, 8x8 register blocking, K-chunks of 64 ----
__global__ void __launch_bounds__(256) k_gemm(const float* __restrict__ x,
                                              const float* __restrict__ W, int n) {
    extern __shared__ float sm[];
    float* xs = sm;              // [64][129] : xs[k*129 + row] (transposed)
    float* ws = sm + 64 * 129;   // [64][128] : ws[k*128 + col]
    int tid = threadIdx.x;
    int tx = tid & 15, ty = tid >> 4;
    int rowBase = blockIdx.x * 128;

    float acc[8][8];
#pragma unroll
    for (int i = 0; i < 8; i++)
#pragma unroll
        for (int j = 0; j < 8; j++) acc[i][j] = 0.f;

    for (int kc = 0; kc < 128; kc += 64) {
        for (int i = tid; i < 2048; i += 256) {
            int row = i >> 4;
            int k4 = (i & 15) << 2;
            float4 v = make_float4(0.f, 0.f, 0.f, 0.f);
            int gr = rowBase + row;
            if (gr < n) v = *(const float4*)(x + (size_t)gr * NF + kc + k4);
            xs[(k4 + 0) * 129 + row] = v.x;
            xs[(k4 + 1) * 129 + row] = v.y;
            xs[(k4 + 2) * 129 + row] = v.z;
            xs[(k4 + 3) * 129 + row] = v.w;
        }
        for (int i = tid; i < 2048; i += 256) {
            int k = i >> 5;
            int c4 = (i & 31) << 2;
            *(float4*)(ws + k * NF + c4) =
                *(const float4*)(W + (size_t)(kc + k) * NF + c4);
        }
        __syncthreads();

        for (int k = 0; k < 64; k++) {
            float a[8], b[8];
#pragma unroll
            for (int i = 0; i < 8; i++) a[i] = xs[k * 129 + ty * 8 + i];
            float4 b0 = *(float4*)(ws + k * NF + tx * 8);
            float4 b1 = *(float4*)(ws + k * NF + tx * 8 + 4);
            b[0] = b0.x; b[1] = b0.y; b[2] = b0.z; b[3] = b0.w;
            b[4] = b1.x; b[5] = b1.y; b[6] = b1.z; b[7] = b1.w;
#pragma unroll
            for (int i = 0; i < 8; i++)
#pragma unroll
                for (int j = 0; j < 8; j++) acc[i][j] += a[i] * b[j];
        }
        __syncthreads();
    }

#pragma unroll
    for (int i = 0; i < 8; i++) {
        int gr = rowBase + ty * 8 + i;
        if (gr < n) {
            float4 o0 = make_float4(acc[i][0], acc[i][1], acc[i][2], acc[i][3]);
            float4 o1 = make_float4(acc[i][4], acc[i][5], acc[i][6], acc[i][7]);
            *(float4*)(g_h + (size_t)gr * NF + tx * 8) = o0;
            *(float4*)(g_h + (size_t)gr * NF + tx * 8 + 4) = o1;
        }
    }
}

// ---- agg init: self-loop contribution + bias ----
__global__ void k_self(const float* __restrict__ b, int n) {
    int i = blockIdx.x * blockDim.x + threadIdx.x;   // over n*32 float4 groups
    if (i < n * 32) {
        int r = i >> 5;
        float dd = g_dis[r];
        dd = dd * dd;
        int f4 = (i & 31) << 2;
        float4 hv = *(const float4*)(g_h + (size_t)r * NF + f4);
        float4 bv = *(const float4*)(b + f4);
        float4 o = make_float4(hv.x * dd + bv.x, hv.y * dd + bv.y,
                               hv.z * dd + bv.z, hv.w * dd + bv.w);
        *(float4*)(g_agg + (size_t)r * NF + f4) = o;
    }
}

// ---- per-edge scatter: one warp per edge, float4 gather + red.v4 ----
__global__ void k_scatter(const int* __restrict__ ei, int E) {
    int g = blockIdx.x * blockDim.x + threadIdx.x;
    int e = g >> 5;
    int lane = g & 31;
    if (e < E) {
        int s = ei[e];
        int d = ei[E + e];
        float w = g_dis[s] * g_dis[d];
        float4 v = *(const float4*)(g_h + (size_t)s * NF + lane * 4);
        float4 sv = make_float4(v.x * w, v.y * w, v.z * w, v.w * w);
        red_add_v4(g_agg + (size_t)d * NF + lane * 4, sv);
    }
}

// ---- per-feature sum / sumsq ----
__global__ void k_stats(int n) {
    int f = threadIdx.x;   // 128 threads
    float s = 0.f, s2 = 0.f;
    for (int r = blockIdx.x; r < n; r += gridDim.x) {
        float v = g_agg[(size_t)r * NF + f];
        s += v;
        s2 += v * v;
    }
    atomicAdd(&g_sum[f], s);
    atomicAdd(&g_sumsq[f], s2);
}

// ---- finalize stats: shift/scale per feature ----
__global__ void k_fin(const float* __restrict__ gw, const float* __restrict__ gb,
                      const float* __restrict__ gms, float inv_n) {
    int f = threadIdx.x;
    float mean = g_sum[f] * inv_n;
    float ex2 = g_sumsq[f] * inv_n;
    float c = mean * gms[f];
    float var = ex2 - 2.f * c * mean + c * c;
    float sc = rsqrtf(var + 1e-5f) * gw[f];
    g_shift[f] = c;
    g_scale[f] = sc;
    g_beta[f] = gb[f];
}

// ---- normalize + LeakyReLU + write out ----
__global__ void k_out(float* __restrict__ out, int n) {
    int i = blockIdx.x * blockDim.x + threadIdx.x;   // over n*32 float4 groups
    if (i < n * 32) {
        int f4 = (i & 31) << 2;
        float4 v = *(const float4*)(g_agg + (size_t)i * 4);
        float4 o;
        o.x = (v.x - g_shift[f4 + 0]) * g_scale[f4 + 0] + g_beta[f4 + 0];
        o.y = (v.y - g_shift[f4 + 1]) * g_scale[f4 + 1] + g_beta[f4 + 1];
        o.z = (v.z - g_shift[f4 + 2]) * g_scale[f4 + 2] + g_beta[f4 + 2];
        o.w = (v.w - g_shift[f4 + 3]) * g_scale[f4 + 3] + g_beta[f4 + 3];
        o.x = o.x > 0.f ? o.x : 0.01f * o.x;
        o.y = o.y > 0.f ? o.y : 0.01f * o.y;
        o.z = o.z > 0.f ? o.z : 0.01f * o.z;
        o.w = o.w > 0.f ? o.w : 0.01f * o.w;
        *(float4*)(out + (size_t)i * 4) = o;
    }
}

// ---- second output: edge_index cast to out dtype (exact for idx < 2^24) ----
__global__ void k_edges(const int* __restrict__ ei, float* __restrict__ out,
                        int m, int lim) {
    int i = blockIdx.x * blockDim.x + threadIdx.x;
    if (i < m && i < lim) out[i] = (float)ei[i];
}

extern "C" void kernel_launch(void* const* d_in, const int* in_sizes, int n_in,
                              void* d_out, int out_size) {
    const float* x = (const float*)d_in[0];
    const int* ei = (const int*)d_in[1];
    const float* W = (const float*)d_in[2];
    const float* b = (const float*)d_in[3];
    const float* gw = (const float*)d_in[4];
    const float* gb = (const float*)d_in[5];
    const float* gms = (const float*)d_in[6];

    int n = in_sizes[0] / NF;
    int E = in_sizes[1] / 2;
    float* out = (float*)d_out;

    cudaFuncSetAttribute(k_gemm, cudaFuncAttributeMaxDynamicSharedMemorySize,
                         (64 * 129 + 64 * 128) * 4);

    int init_n = (n > NF ? n : NF);
    k_init<<<(init_n + 255) / 256, 256>>>(n);
    k_deg<<<(E + 255) / 256, 256>>>(ei, E);
    k_dis<<<(n + 255) / 256, 256>>>(n);
    k_gemm<<<(n + 127) / 128, 256, (64 * 129 + 64 * 128) * 4>>>(x, W, n);
    k_self<<<(n * 32 + 255) / 256, 256>>>(b, n);
    {
        long long total = (long long)E * 32;
        int blocks = (int)((total + 255) / 256);
        k_scatter<<<blocks, 256>>>(ei, E);
    }
    k_stats<<<512, 128>>>(n);
    k_fin<<<1, 128>>>(gw, gb, gms, 1.0f / (float)n);
    k_out<<<(n * 32 + 255) / 256, 256>>>(out, n);

    long long extra = (long long)out_size - (long long)n * NF;
    if (extra > 0) {
        int m = (int)extra;
        k_edges<<<(m + 255) / 256, 256>>>(ei, out + (size_t)n * NF, m, in_sizes[1]);
    }
}

// round 3
// speedup vs baseline: 1.2012x; 1.2012x over previous
#include <cuda_runtime.h>

#define NF 128
#define MAXN 100000
#define MAXE 2000000

// ---- scratch (device globals: no allocation allowed) ----
__device__ int   g_cnt[MAXN];     // in-degree (excluding self loop)
__device__ int   g_off[MAXN];     // CSR exclusive offsets
__device__ int   g_fill[MAXN];    // bucket fill counters
__device__ int   g_bsum[1024];    // block sums for scan
__device__ int   g_src[MAXE];     // bucketed source indices
__device__ float g_dis[MAXN];
__device__ float g_h[(size_t)MAXN * NF];
__device__ float g_agg[(size_t)MAXN * NF];
__device__ float g_sum[NF];
__device__ float g_sumsq[NF];
__device__ float g_shift[NF];
__device__ float g_scale[NF];
__device__ float g_beta[NF];

// ---- init: zero counters + stats ----
__global__ void k_init(int n) {
    int i = blockIdx.x * blockDim.x + threadIdx.x;
    if (i < NF) { g_sum[i] = 0.f; g_sumsq[i] = 0.f; }
    if (i < n) { g_cnt[i] = 0; g_fill[i] = 0; }
}

// ---- degree count over dst ----
__global__ void k_deg(const int* __restrict__ ei, int E) {
    int i = blockIdx.x * blockDim.x + threadIdx.x;
    if (i < E) atomicAdd(&g_cnt[ei[E + i]], 1);
}

__global__ void k_dis(int n) {
    int i = blockIdx.x * blockDim.x + threadIdx.x;
    if (i < n) g_dis[i] = rsqrtf((float)(g_cnt[i] + 1));
}

// ---- prefix scan (3 stages) ----
__global__ void k_scan_block(int n) {
    __shared__ int sm[256];
    int i = blockIdx.x * 256 + threadIdx.x;
    int v = (i < n) ? g_cnt[i] : 0;
    sm[threadIdx.x] = v; __syncthreads();
    for (int ofs = 1; ofs < 256; ofs <<= 1) {
        int x = (threadIdx.x >= ofs) ? sm[threadIdx.x - ofs] : 0;
        __syncthreads();
        sm[threadIdx.x] += x;
        __syncthreads();
    }
    if (i < n) g_off[i] = sm[threadIdx.x] - v;     // exclusive within block
    if (threadIdx.x == 255) g_bsum[blockIdx.x] = sm[255];
}

__global__ void k_scan_top(int nb) {
    __shared__ int sm[1024];
    int t = threadIdx.x;
    int v = (t < nb) ? g_bsum[t] : 0;
    sm[t] = v; __syncthreads();
    for (int ofs = 1; ofs < 1024; ofs <<= 1) {
        int x = (t >= ofs) ? sm[t - ofs] : 0;
        __syncthreads();
        sm[t] += x;
        __syncthreads();
    }
    if (t < nb) g_bsum[t] = sm[t] - v;             // exclusive block base
}

__global__ void k_scan_add(int n) {
    int i = blockIdx.x * 256 + threadIdx.x;
    if (i < n) g_off[i] += g_bsum[blockIdx.x];
}

// ---- bucket edges by dst ----
__global__ void k_bucket(const int* __restrict__ ei, int E) {
    int i = blockIdx.x * blockDim.x + threadIdx.x;
    if (i < E) {
        int s = ei[i];
        int d = ei[E + i];
        int slot = g_off[d] + atomicAdd(&g_fill[d], 1);
        g_src[slot] = s;
    }
}

// ---- GEMM: h = x @ W. 128x128 tile, 8x8 register blocking ----
__global__ void __launch_bounds__(256) k_gemm(const float* __restrict__ x,
                                              const float* __restrict__ W, int n) {
    extern __shared__ float sm[];
    float* xs = sm;              // [64][132] : xs[k*132 + row] (transposed, 16B-aligned rows)
    float* ws = sm + 64 * 132;   // [64][128] : ws[k*128 + col]
    int tid = threadIdx.x;
    int tx = tid & 15, ty = tid >> 4;
    int rowBase = blockIdx.x * 128;

    float acc[8][8];
#pragma unroll
    for (int i = 0; i < 8; i++)
#pragma unroll
        for (int j = 0; j < 8; j++) acc[i][j] = 0.f;

    for (int kc = 0; kc < 128; kc += 64) {
        for (int i = tid; i < 2048; i += 256) {
            int row = i >> 4;
            int k4 = (i & 15) << 2;
            float4 v = make_float4(0.f, 0.f, 0.f, 0.f);
            int gr = rowBase + row;
            if (gr < n) v = *(const float4*)(x + (size_t)gr * NF + kc + k4);
            xs[(k4 + 0) * 132 + row] = v.x;
            xs[(k4 + 1) * 132 + row] = v.y;
            xs[(k4 + 2) * 132 + row] = v.z;
            xs[(k4 + 3) * 132 + row] = v.w;
        }
        for (int i = tid; i < 2048; i += 256) {
            int k = i >> 5;
            int c4 = (i & 31) << 2;
            *(float4*)(ws + k * NF + c4) =
                *(const float4*)(W + (size_t)(kc + k) * NF + c4);
        }
        __syncthreads();

        for (int k = 0; k < 64; k++) {
            float4 a0 = *(float4*)(xs + k * 132 + ty * 8);
            float4 a1 = *(float4*)(xs + k * 132 + ty * 8 + 4);
            float4 b0 = *(float4*)(ws + k * NF + tx * 8);
            float4 b1 = *(float4*)(ws + k * NF + tx * 8 + 4);
            float a[8] = {a0.x, a0.y, a0.z, a0.w, a1.x, a1.y, a1.z, a1.w};
            float b[8] = {b0.x, b0.y, b0.z, b0.w, b1.x, b1.y, b1.z, b1.w};
#pragma unroll
            for (int i = 0; i < 8; i++)
#pragma unroll
                for (int j = 0; j < 8; j++) acc[i][j] += a[i] * b[j];
        }
        __syncthreads();
    }

#pragma unroll
    for (int i = 0; i < 8; i++) {
        int gr = rowBase + ty * 8 + i;
        if (gr < n) {
            float4 o0 = make_float4(acc[i][0], acc[i][1], acc[i][2], acc[i][3]);
            float4 o1 = make_float4(acc[i][4], acc[i][5], acc[i][6], acc[i][7]);
            *(float4*)(g_h + (size_t)gr * NF + tx * 8) = o0;
            *(float4*)(g_h + (size_t)gr * NF + tx * 8 + 4) = o1;
        }
    }
}

// ---- CSR aggregate: one warp per node, register accumulation ----
__global__ void __launch_bounds__(256) k_agg(const float* __restrict__ b, int n) {
    int warpsPerGrid = gridDim.x * 8;
    int lane = threadIdx.x & 31;
    for (int d = blockIdx.x * 8 + (threadIdx.x >> 5); d < n; d += warpsPerGrid) {
        int beg = g_off[d];
        int cnt = g_cnt[d];
        float dd = g_dis[d];
        float4 acc = *(const float4*)(g_h + (size_t)d * NF + lane * 4);
        acc.x *= dd; acc.y *= dd; acc.z *= dd; acc.w *= dd;

        int j = 0;
        for (; j + 4 <= cnt; j += 4) {
            int s0 = g_src[beg + j + 0];
            int s1 = g_src[beg + j + 1];
            int s2 = g_src[beg + j + 2];
            int s3 = g_src[beg + j + 3];
            float w0 = g_dis[s0], w1 = g_dis[s1], w2 = g_dis[s2], w3 = g_dis[s3];
            float4 v0 = *(const float4*)(g_h + (size_t)s0 * NF + lane * 4);
            float4 v1 = *(const float4*)(g_h + (size_t)s1 * NF + lane * 4);
            float4 v2 = *(const float4*)(g_h + (size_t)s2 * NF + lane * 4);
            float4 v3 = *(const float4*)(g_h + (size_t)s3 * NF + lane * 4);
            acc.x += w0 * v0.x + w1 * v1.x + w2 * v2.x + w3 * v3.x;
            acc.y += w0 * v0.y + w1 * v1.y + w2 * v2.y + w3 * v3.y;
            acc.z += w0 * v0.z + w1 * v1.z + w2 * v2.z + w3 * v3.z;
            acc.w += w0 * v0.w + w1 * v1.w + w2 * v2.w + w3 * v3.w;
        }
        for (; j < cnt; j++) {
            int s = g_src[beg + j];
            float w = g_dis[s];
            float4 v = *(const float4*)(g_h + (size_t)s * NF + lane * 4);
            acc.x += w * v.x; acc.y += w * v.y; acc.z += w * v.z; acc.w += w * v.w;
        }

        float4 bv = *(const float4*)(b + lane * 4);
        float4 o = make_float4(acc.x * dd + bv.x, acc.y * dd + bv.y,
                               acc.z * dd + bv.z, acc.w * dd + bv.w);
        *(float4*)(g_agg + (size_t)d * NF + lane * 4) = o;
    }
}

// ---- per-feature sum / sumsq ----
__global__ void k_stats(int n) {
    int f = threadIdx.x;   // 128 threads
    float s = 0.f, s2 = 0.f;
    for (int r = blockIdx.x; r < n; r += gridDim.x) {
        float v = g_agg[(size_t)r * NF + f];
        s += v;
        s2 += v * v;
    }
    atomicAdd(&g_sum[f], s);
    atomicAdd(&g_sumsq[f], s2);
}

// ---- finalize stats ----
__global__ void k_fin(const float* __restrict__ gw, const float* __restrict__ gb,
                      const float* __restrict__ gms, float inv_n) {
    int f = threadIdx.x;
    float mean = g_sum[f] * inv_n;
    float ex2 = g_sumsq[f] * inv_n;
    float c = mean * gms[f];
    float var = ex2 - 2.f * c * mean + c * c;
    float sc = rsqrtf(var + 1e-5f) * gw[f];
    g_shift[f] = c;
    g_scale[f] = sc;
    g_beta[f] = gb[f];
}

// ---- normalize + LeakyReLU + write out ----
__global__ void k_out(float* __restrict__ out, int n) {
    int i = blockIdx.x * blockDim.x + threadIdx.x;   // over n*32 float4 groups
    if (i < n * 32) {
        int f4 = (i & 31) << 2;
        float4 v = *(const float4*)(g_agg + (size_t)i * 4);
        float4 o;
        o.x = (v.x - g_shift[f4 + 0]) * g_scale[f4 + 0] + g_beta[f4 + 0];
        o.y = (v.y - g_shift[f4 + 1]) * g_scale[f4 + 1] + g_beta[f4 + 1];
        o.z = (v.z - g_shift[f4 + 2]) * g_scale[f4 + 2] + g_beta[f4 + 2];
        o.w = (v.w - g_shift[f4 + 3]) * g_scale[f4 + 3] + g_beta[f4 + 3];
        o.x = o.x > 0.f ? o.x : 0.01f * o.x;
        o.y = o.y > 0.f ? o.y : 0.01f * o.y;
        o.z = o.z > 0.f ? o.z : 0.01f * o.z;
        o.w = o.w > 0.f ? o.w : 0.01f * o.w;
        *(float4*)(out + (size_t)i * 4) = o;
    }
}

// ---- second output: edge_index cast to out dtype ----
__global__ void k_edges(const int* __restrict__ ei, float* __restrict__ out,
                        int m, int lim) {
    int i = blockIdx.x * blockDim.x + threadIdx.x;
    if (i < m && i < lim) out[i] = (float)ei[i];
}

extern "C" void kernel_launch(void* const* d_in, const int* in_sizes, int n_in,
                              void* d_out, int out_size) {
    const float* x = (const float*)d_in[0];
    const int* ei = (const int*)d_in[1];
    const float* W = (const float*)d_in[2];
    const float* b = (const float*)d_in[3];
    const float* gw = (const float*)d_in[4];
    const float* gb = (const float*)d_in[5];
    const float* gms = (const float*)d_in[6];

    int n = in_sizes[0] / NF;
    int E = in_sizes[1] / 2;
    float* out = (float*)d_out;

    int smem = (64 * 132 + 64 * 128) * 4;
    cudaFuncSetAttribute(k_gemm, cudaFuncAttributeMaxDynamicSharedMemorySize, smem);

    int init_n = (n > NF ? n : NF);
    int NB = (n + 255) / 256;

    k_init<<<(init_n + 255) / 256, 256>>>(n);
    k_deg<<<(E + 255) / 256, 256>>>(ei, E);
    k_dis<<<(n + 255) / 256, 256>>>(n);
    k_scan_block<<<NB, 256>>>(n);
    k_scan_top<<<1, 1024>>>(NB);
    k_scan_add<<<NB, 256>>>(n);
    k_bucket<<<(E + 255) / 256, 256>>>(ei, E);
    k_gemm<<<(n + 127) / 128, 256, smem>>>(x, W, n);
    k_agg<<<(n + 7) / 8, 256>>>(b, n);
    k_stats<<<512, 128>>>(n);
    k_fin<<<1, 128>>>(gw, gb, gms, 1.0f / (float)n);
    k_out<<<(n * 32 + 255) / 256, 256>>>(out, n);

    long long extra = (long long)out_size - (long long)n * NF;
    if (extra > 0) {
        int m = (int)extra;
        k_edges<<<(m + 255) / 256, 256>>>(ei, out + (size_t)n * NF, m, in_sizes[1]);
    }
}

// round 4
// speedup vs baseline: 1.6368x; 1.3627x over previous
#include <cuda_runtime.h>

#define NF 128
#define MAXN 100000
#define MAXE 2000000

// ---- scratch (device globals: no allocation allowed) ----
__device__ int   g_cnt[MAXN];     // in-degree (excluding self loop)
__device__ int   g_off[MAXN];     // CSR exclusive offsets
__device__ int   g_fill[MAXN];    // bucket fill counters
__device__ int   g_bsum[1024];    // block sums for scan
__device__ int   g_src[MAXE];     // bucketed source indices
__device__ float g_dis[MAXN];
__device__ float g_h[(size_t)MAXN * NF];
__device__ float g_agg[(size_t)MAXN * NF];
__device__ float g_sum[NF];
__device__ float g_sumsq[NF];
__device__ float g_shift[NF];
__device__ float g_scale[NF];
__device__ float g_beta[NF];

// ---- packed f32x2 FMA (ptxas never emits FFMA2 from C++) ----
__device__ __forceinline__ void fma_f32x2(unsigned long long& acc,
                                          unsigned long long a,
                                          unsigned long long b) {
    asm("fma.rn.f32x2 %0, %1, %2, %0;" : "+l"(acc) : "l"(a), "l"(b));
}
__device__ __forceinline__ unsigned long long dup_f32x2(float v) {
    unsigned long long r;
    unsigned int u = __float_as_uint(v);
    asm("mov.b64 %0, {%1, %1};" : "=l"(r) : "r"(u));
    return r;
}
__device__ __forceinline__ float2 unpack_f32x2(unsigned long long p) {
    unsigned int lo, hi;
    asm("mov.b64 {%0, %1}, %2;" : "=r"(lo), "=r"(hi) : "l"(p));
    return make_float2(__uint_as_float(lo), __uint_as_float(hi));
}

// ---- init: zero counters + stats ----
__global__ void k_init(int n) {
    int i = blockIdx.x * blockDim.x + threadIdx.x;
    if (i < NF) { g_sum[i] = 0.f; g_sumsq[i] = 0.f; }
    if (i < n) { g_cnt[i] = 0; g_fill[i] = 0; }
}

// ---- degree count over dst ----
__global__ void k_deg(const int* __restrict__ ei, int E) {
    int i = blockIdx.x * blockDim.x + threadIdx.x;
    if (i < E) atomicAdd(&g_cnt[ei[E + i]], 1);
}

__global__ void k_dis(int n) {
    int i = blockIdx.x * blockDim.x + threadIdx.x;
    if (i < n) g_dis[i] = rsqrtf((float)(g_cnt[i] + 1));
}

// ---- prefix scan (3 stages) ----
__global__ void k_scan_block(int n) {
    __shared__ int sm[256];
    int i = blockIdx.x * 256 + threadIdx.x;
    int v = (i < n) ? g_cnt[i] : 0;
    sm[threadIdx.x] = v; __syncthreads();
    for (int ofs = 1; ofs < 256; ofs <<= 1) {
        int x = (threadIdx.x >= ofs) ? sm[threadIdx.x - ofs] : 0;
        __syncthreads();
        sm[threadIdx.x] += x;
        __syncthreads();
    }
    if (i < n) g_off[i] = sm[threadIdx.x] - v;
    if (threadIdx.x == 255) g_bsum[blockIdx.x] = sm[255];
}

__global__ void k_scan_top(int nb) {
    __shared__ int sm[1024];
    int t = threadIdx.x;
    int v = (t < nb) ? g_bsum[t] : 0;
    sm[t] = v; __syncthreads();
    for (int ofs = 1; ofs < 1024; ofs <<= 1) {
        int x = (t >= ofs) ? sm[t - ofs] : 0;
        __syncthreads();
        sm[t] += x;
        __syncthreads();
    }
    if (t < nb) g_bsum[t] = sm[t] - v;
}

__global__ void k_scan_add(int n) {
    int i = blockIdx.x * 256 + threadIdx.x;
    if (i < n) g_off[i] += g_bsum[blockIdx.x];
}

// ---- bucket edges by dst ----
__global__ void k_bucket(const int* __restrict__ ei, int E) {
    int i = blockIdx.x * blockDim.x + threadIdx.x;
    if (i < E) {
        int s = ei[i];
        int d = ei[E + i];
        int slot = g_off[d] + atomicAdd(&g_fill[d], 1);
        g_src[slot] = s;
    }
}

// ---- GEMM: h = x @ W. 128x128 tile, 8x8 register blocking, FFMA2 inner ----
__global__ void __launch_bounds__(256) k_gemm(const float* __restrict__ x,
                                              const float* __restrict__ W, int n) {
    extern __shared__ float sm[];
    float* xs = sm;              // [64][132] : xs[k*132 + row]
    float* ws = sm + 64 * 132;   // [64][128] : ws[k*128 + col]
    int tid = threadIdx.x;
    int tx = tid & 15, ty = tid >> 4;
    int rowBase = blockIdx.x * 128;

    unsigned long long acc[8][4];
#pragma unroll
    for (int i = 0; i < 8; i++)
#pragma unroll
        for (int j = 0; j < 4; j++) acc[i][j] = 0ULL;

    for (int kc = 0; kc < 128; kc += 64) {
        for (int i = tid; i < 2048; i += 256) {
            int row = i >> 4;
            int k4 = (i & 15) << 2;
            float4 v = make_float4(0.f, 0.f, 0.f, 0.f);
            int gr = rowBase + row;
            if (gr < n) v = *(const float4*)(x + (size_t)gr * NF + kc + k4);
            xs[(k4 + 0) * 132 + row] = v.x;
            xs[(k4 + 1) * 132 + row] = v.y;
            xs[(k4 + 2) * 132 + row] = v.z;
            xs[(k4 + 3) * 132 + row] = v.w;
        }
        for (int i = tid; i < 2048; i += 256) {
            int k = i >> 5;
            int c4 = (i & 31) << 2;
            *(float4*)(ws + k * NF + c4) =
                *(const float4*)(W + (size_t)(kc + k) * NF + c4);
        }
        __syncthreads();

        for (int k = 0; k < 64; k++) {
            float4 a0 = *(float4*)(xs + k * 132 + ty * 8);
            float4 a1 = *(float4*)(xs + k * 132 + ty * 8 + 4);
            ulonglong2 B0 = *(ulonglong2*)(ws + k * NF + tx * 8);      // cols 0-3
            ulonglong2 B1 = *(ulonglong2*)(ws + k * NF + tx * 8 + 4);  // cols 4-7
            unsigned long long b2[4] = {B0.x, B0.y, B1.x, B1.y};
            unsigned long long a2[8];
            a2[0] = dup_f32x2(a0.x); a2[1] = dup_f32x2(a0.y);
            a2[2] = dup_f32x2(a0.z); a2[3] = dup_f32x2(a0.w);
            a2[4] = dup_f32x2(a1.x); a2[5] = dup_f32x2(a1.y);
            a2[6] = dup_f32x2(a1.z); a2[7] = dup_f32x2(a1.w);
#pragma unroll
            for (int i = 0; i < 8; i++)
#pragma unroll
                for (int j = 0; j < 4; j++) fma_f32x2(acc[i][j], a2[i], b2[j]);
        }
        __syncthreads();
    }

#pragma unroll
    for (int i = 0; i < 8; i++) {
        int gr = rowBase + ty * 8 + i;
        if (gr < n) {
            float2 c0 = unpack_f32x2(acc[i][0]);
            float2 c1 = unpack_f32x2(acc[i][1]);
            float2 c2 = unpack_f32x2(acc[i][2]);
            float2 c3 = unpack_f32x2(acc[i][3]);
            float4 o0 = make_float4(c0.x, c0.y, c1.x, c1.y);
            float4 o1 = make_float4(c2.x, c2.y, c3.x, c3.y);
            *(float4*)(g_h + (size_t)gr * NF + tx * 8) = o0;
            *(float4*)(g_h + (size_t)gr * NF + tx * 8 + 4) = o1;
        }
    }
}

// ---- CSR aggregate: one warp per node + fused GraphNorm stats ----
__global__ void __launch_bounds__(256) k_agg(const float* __restrict__ b, int n) {
    __shared__ float ssum[8 * 128];
    __shared__ float ssq[8 * 128];
    int warpsPerGrid = gridDim.x * 8;
    int w = threadIdx.x >> 5;
    int lane = threadIdx.x & 31;
    float4 bv = *(const float4*)(b + lane * 4);

    float4 ls = make_float4(0.f, 0.f, 0.f, 0.f);    // local sum
    float4 lq = make_float4(0.f, 0.f, 0.f, 0.f);    // local sumsq

    for (int d = blockIdx.x * 8 + w; d < n; d += warpsPerGrid) {
        int beg = g_off[d];
        int cnt = g_cnt[d];
        float dd = g_dis[d];
        float4 acc = *(const float4*)(g_h + (size_t)d * NF + lane * 4);
        acc.x *= dd; acc.y *= dd; acc.z *= dd; acc.w *= dd;

        int j = 0;
        for (; j + 4 <= cnt; j += 4) {
            int s0 = g_src[beg + j + 0];
            int s1 = g_src[beg + j + 1];
            int s2 = g_src[beg + j + 2];
            int s3 = g_src[beg + j + 3];
            float w0 = g_dis[s0], w1 = g_dis[s1], w2 = g_dis[s2], w3 = g_dis[s3];
            float4 v0 = *(const float4*)(g_h + (size_t)s0 * NF + lane * 4);
            float4 v1 = *(const float4*)(g_h + (size_t)s1 * NF + lane * 4);
            float4 v2 = *(const float4*)(g_h + (size_t)s2 * NF + lane * 4);
            float4 v3 = *(const float4*)(g_h + (size_t)s3 * NF + lane * 4);
            acc.x += w0 * v0.x + w1 * v1.x + w2 * v2.x + w3 * v3.x;
            acc.y += w0 * v0.y + w1 * v1.y + w2 * v2.y + w3 * v3.y;
            acc.z += w0 * v0.z + w1 * v1.z + w2 * v2.z + w3 * v3.z;
            acc.w += w0 * v0.w + w1 * v1.w + w2 * v2.w + w3 * v3.w;
        }
        for (; j < cnt; j++) {
            int s = g_src[beg + j];
            float ww = g_dis[s];
            float4 v = *(const float4*)(g_h + (size_t)s * NF + lane * 4);
            acc.x += ww * v.x; acc.y += ww * v.y; acc.z += ww * v.z; acc.w += ww * v.w;
        }

        float4 o = make_float4(acc.x * dd + bv.x, acc.y * dd + bv.y,
                               acc.z * dd + bv.z, acc.w * dd + bv.w);
        *(float4*)(g_agg + (size_t)d * NF + lane * 4) = o;

        ls.x += o.x; ls.y += o.y; ls.z += o.z; ls.w += o.w;
        lq.x += o.x * o.x; lq.y += o.y * o.y; lq.z += o.z * o.z; lq.w += o.w * o.w;
    }

    *(float4*)(ssum + w * 128 + lane * 4) = ls;
    *(float4*)(ssq + w * 128 + lane * 4) = lq;
    __syncthreads();

    if (threadIdx.x < 128) {
        int f = threadIdx.x;
        float s = 0.f, q = 0.f;
#pragma unroll
        for (int k = 0; k < 8; k++) { s += ssum[k * 128 + f]; q += ssq[k * 128 + f]; }
        atomicAdd(&g_sum[f], s);
        atomicAdd(&g_sumsq[f], q);
    }
}

// ---- finalize stats ----
__global__ void k_fin(const float* __restrict__ gw, const float* __restrict__ gb,
                      const float* __restrict__ gms, float inv_n) {
    int f = threadIdx.x;
    float mean = g_sum[f] * inv_n;
    float ex2 = g_sumsq[f] * inv_n;
    float c = mean * gms[f];
    float var = ex2 - 2.f * c * mean + c * c;
    float sc = rsqrtf(var + 1e-5f) * gw[f];
    g_shift[f] = c;
    g_scale[f] = sc;
    g_beta[f] = gb[f];
}

// ---- normalize + LeakyReLU + edge copy, single kernel ----
__global__ void k_out(const int* __restrict__ ei, float* __restrict__ out,
                      int n, int m2) {
    int i = blockIdx.x * blockDim.x + threadIdx.x;
    int nodeGroups = n * 32;
    if (i < nodeGroups) {
        int f4 = (i & 31) << 2;
        float4 v = *(const float4*)(g_agg + (size_t)i * 4);
        float4 o;
        o.x = (v.x - g_shift[f4 + 0]) * g_scale[f4 + 0] + g_beta[f4 + 0];
        o.y = (v.y - g_shift[f4 + 1]) * g_scale[f4 + 1] + g_beta[f4 + 1];
        o.z = (v.z - g_shift[f4 + 2]) * g_scale[f4 + 2] + g_beta[f4 + 2];
        o.w = (v.w - g_shift[f4 + 3]) * g_scale[f4 + 3] + g_beta[f4 + 3];
        o.x = o.x > 0.f ? o.x : 0.01f * o.x;
        o.y = o.y > 0.f ? o.y : 0.01f * o.y;
        o.z = o.z > 0.f ? o.z : 0.01f * o.z;
        o.w = o.w > 0.f ? o.w : 0.01f * o.w;
        *(float4*)(out + (size_t)i * 4) = o;
    } else {
        int g = i - nodeGroups;          // edge float4 group
        int base = g * 4;
        if (base < m2) {
            float* dst = out + (size_t)n * NF + base;
            if (base + 4 <= m2) {
                int4 e = *(const int4*)(ei + base);
                float4 o = make_float4((float)e.x, (float)e.y, (float)e.z, (float)e.w);
                *(float4*)dst = o;
            } else {
                for (int k = 0; base + k < m2; k++) dst[k] = (float)ei[base + k];
            }
        }
    }
}

extern "C" void kernel_launch(void* const* d_in, const int* in_sizes, int n_in,
                              void* d_out, int out_size) {
    const float* x = (const float*)d_in[0];
    const int* ei = (const int*)d_in[1];
    const float* W = (const float*)d_in[2];
    const float* b = (const float*)d_in[3];
    const float* gw = (const float*)d_in[4];
    const float* gb = (const float*)d_in[5];
    const float* gms = (const float*)d_in[6];

    int n = in_sizes[0] / NF;
    int E = in_sizes[1] / 2;
    float* out = (float*)d_out;

    int smem = (64 * 132 + 64 * 128) * 4;
    cudaFuncSetAttribute(k_gemm, cudaFuncAttributeMaxDynamicSharedMemorySize, smem);

    int init_n = (n > NF ? n : NF);
    int NB = (n + 255) / 256;

    k_init<<<(init_n + 255) / 256, 256>>>(n);
    k_deg<<<(E + 255) / 256, 256>>>(ei, E);
    k_dis<<<(n + 255) / 256, 256>>>(n);
    k_scan_block<<<NB, 256>>>(n);
    k_scan_top<<<1, 1024>>>(NB);
    k_scan_add<<<NB, 256>>>(n);
    k_bucket<<<(E + 255) / 256, 256>>>(ei, E);
    k_gemm<<<(n + 127) / 128, 256, smem>>>(x, W, n);

    int aggBlocks = (n + 7) / 8;
    if (aggBlocks > 1184) aggBlocks = 1184;
    k_agg<<<aggBlocks, 256>>>(b, n);

    k_fin<<<1, 128>>>(gw, gb, gms, 1.0f / (float)n);

    long long extra = (long long)out_size - (long long)n * NF;
    int m2 = 0;
    if (extra > 0) {
        m2 = (int)(extra < (long long)in_sizes[1] ? extra : (long long)in_sizes[1]);
    }
    long long totalThreads = (long long)n * 32 + (m2 + 3) / 4;
    k_out<<<(int)((totalThreads + 255) / 256), 256>>>(ei, out, n, m2);
}

// round 5
// speedup vs baseline: 1.9474x; 1.1897x over previous
#include <cuda_runtime.h>

#define NF 128
#define MAXN 100000
#define MAXE 2000000

// ---- scratch (device globals: no allocation allowed) ----
__device__ int   g_cnt[MAXN];     // in-degree (excluding self loop)
__device__ int   g_off[MAXN];     // CSR exclusive offsets
__device__ int   g_fill[MAXN];    // bucket fill counters
__device__ int   g_bsum[1024];    // block sums for scan
__device__ int   g_src[MAXE];     // bucketed source indices
__device__ float g_dis[MAXN];
__device__ float g_h[(size_t)MAXN * NF];
__device__ float g_agg[(size_t)MAXN * NF];
__device__ float g_sum[NF];
__device__ float g_sumsq[NF];
__device__ float g_shift[NF];
__device__ float g_scale[NF];
__device__ float g_beta[NF];

// ---- packed f32x2 FMA (ptxas never emits FFMA2 from C++) ----
__device__ __forceinline__ void fma_f32x2(unsigned long long& acc,
                                          unsigned long long a,
                                          unsigned long long b) {
    asm("fma.rn.f32x2 %0, %1, %2, %0;" : "+l"(acc) : "l"(a), "l"(b));
}
__device__ __forceinline__ unsigned long long dup_f32x2(float v) {
    unsigned long long r;
    unsigned int u = __float_as_uint(v);
    asm("mov.b64 %0, {%1, %1};" : "=l"(r) : "r"(u));
    return r;
}
__device__ __forceinline__ float2 unpack_f32x2(unsigned long long p) {
    unsigned int lo, hi;
    asm("mov.b64 {%0, %1}, %2;" : "=r"(lo), "=r"(hi) : "l"(p));
    return make_float2(__uint_as_float(lo), __uint_as_float(hi));
}

// ---- init: zero counters + stats ----
__global__ void k_init(int n) {
    int i = blockIdx.x * blockDim.x + threadIdx.x;
    if (i < NF) { g_sum[i] = 0.f; g_sumsq[i] = 0.f; }
    if (i < n) { g_cnt[i] = 0; g_fill[i] = 0; }
}

// ---- degree count over dst ----
__global__ void k_deg(const int* __restrict__ ei, int E) {
    int i = blockIdx.x * blockDim.x + threadIdx.x;
    if (i < E) atomicAdd(&g_cnt[ei[E + i]], 1);
}

// ---- prefix scan (3 stages); stage 1 also emits dis = rsqrt(deg) ----
__global__ void k_scan_block(int n) {
    __shared__ int sm[256];
    int i = blockIdx.x * 256 + threadIdx.x;
    int v = (i < n) ? g_cnt[i] : 0;
    sm[threadIdx.x] = v; __syncthreads();
    for (int ofs = 1; ofs < 256; ofs <<= 1) {
        int x = (threadIdx.x >= ofs) ? sm[threadIdx.x - ofs] : 0;
        __syncthreads();
        sm[threadIdx.x] += x;
        __syncthreads();
    }
    if (i < n) {
        g_off[i] = sm[threadIdx.x] - v;
        g_dis[i] = rsqrtf((float)(v + 1));
    }
    if (threadIdx.x == 255) g_bsum[blockIdx.x] = sm[255];
}

__global__ void k_scan_top(int nb) {
    __shared__ int sm[1024];
    int t = threadIdx.x;
    int v = (t < nb) ? g_bsum[t] : 0;
    sm[t] = v; __syncthreads();
    for (int ofs = 1; ofs < 1024; ofs <<= 1) {
        int x = (t >= ofs) ? sm[t - ofs] : 0;
        __syncthreads();
        sm[t] += x;
        __syncthreads();
    }
    if (t < nb) g_bsum[t] = sm[t] - v;
}

__global__ void k_scan_add(int n) {
    int i = blockIdx.x * 256 + threadIdx.x;
    if (i < n) g_off[i] += g_bsum[blockIdx.x];
}

// ---- bucket edges by dst ----
__global__ void k_bucket(const int* __restrict__ ei, int E) {
    int i = blockIdx.x * blockDim.x + threadIdx.x;
    if (i < E) {
        int s = ei[i];
        int d = ei[E + i];
        int slot = g_off[d] + atomicAdd(&g_fill[d], 1);
        g_src[slot] = s;
    }
}

// ---- GEMM: h = x @ W. 128x128 tile, 8x8 register blocking, FFMA2 inner ----
__global__ void __launch_bounds__(256) k_gemm(const float* __restrict__ x,
                                              const float* __restrict__ W, int n) {
    extern __shared__ float sm[];
    float* xs = sm;              // [64][132]
    float* ws = sm + 64 * 132;   // [64][128]
    int tid = threadIdx.x;
    int tx = tid & 15, ty = tid >> 4;
    int rowBase = blockIdx.x * 128;

    unsigned long long acc[8][4];
#pragma unroll
    for (int i = 0; i < 8; i++)
#pragma unroll
        for (int j = 0; j < 4; j++) acc[i][j] = 0ULL;

    for (int kc = 0; kc < 128; kc += 64) {
        for (int i = tid; i < 2048; i += 256) {
            int row = i >> 4;
            int k4 = (i & 15) << 2;
            float4 v = make_float4(0.f, 0.f, 0.f, 0.f);
            int gr = rowBase + row;
            if (gr < n) v = *(const float4*)(x + (size_t)gr * NF + kc + k4);
            xs[(k4 + 0) * 132 + row] = v.x;
            xs[(k4 + 1) * 132 + row] = v.y;
            xs[(k4 + 2) * 132 + row] = v.z;
            xs[(k4 + 3) * 132 + row] = v.w;
        }
        for (int i = tid; i < 2048; i += 256) {
            int k = i >> 5;
            int c4 = (i & 31) << 2;
            *(float4*)(ws + k * NF + c4) =
                *(const float4*)(W + (size_t)(kc + k) * NF + c4);
        }
        __syncthreads();

        for (int k = 0; k < 64; k++) {
            float4 a0 = *(float4*)(xs + k * 132 + ty * 8);
            float4 a1 = *(float4*)(xs + k * 132 + ty * 8 + 4);
            ulonglong2 B0 = *(ulonglong2*)(ws + k * NF + tx * 8);
            ulonglong2 B1 = *(ulonglong2*)(ws + k * NF + tx * 8 + 4);
            unsigned long long b2[4] = {B0.x, B0.y, B1.x, B1.y};
            unsigned long long a2[8];
            a2[0] = dup_f32x2(a0.x); a2[1] = dup_f32x2(a0.y);
            a2[2] = dup_f32x2(a0.z); a2[3] = dup_f32x2(a0.w);
            a2[4] = dup_f32x2(a1.x); a2[5] = dup_f32x2(a1.y);
            a2[6] = dup_f32x2(a1.z); a2[7] = dup_f32x2(a1.w);
#pragma unroll
            for (int i = 0; i < 8; i++)
#pragma unroll
                for (int j = 0; j < 4; j++) fma_f32x2(acc[i][j], a2[i], b2[j]);
        }
        __syncthreads();
    }

#pragma unroll
    for (int i = 0; i < 8; i++) {
        int gr = rowBase + ty * 8 + i;
        if (gr < n) {
            float2 c0 = unpack_f32x2(acc[i][0]);
            float2 c1 = unpack_f32x2(acc[i][1]);
            float2 c2 = unpack_f32x2(acc[i][2]);
            float2 c3 = unpack_f32x2(acc[i][3]);
            float4 o0 = make_float4(c0.x, c0.y, c1.x, c1.y);
            float4 o1 = make_float4(c2.x, c2.y, c3.x, c3.y);
            *(float4*)(g_h + (size_t)gr * NF + tx * 8) = o0;
            *(float4*)(g_h + (size_t)gr * NF + tx * 8 + 4) = o1;
        }
    }
}

// ---- CSR aggregate: one warp per node + fused GraphNorm stats, 8-edge unroll ----
__global__ void __launch_bounds__(256) k_agg(const float* __restrict__ b, int n) {
    __shared__ float ssum[8 * 128];
    __shared__ float ssq[8 * 128];
    int warpsPerGrid = gridDim.x * 8;
    int w = threadIdx.x >> 5;
    int lane = threadIdx.x & 31;
    float4 bv = *(const float4*)(b + lane * 4);

    float4 ls = make_float4(0.f, 0.f, 0.f, 0.f);
    float4 lq = make_float4(0.f, 0.f, 0.f, 0.f);

    for (int d = blockIdx.x * 8 + w; d < n; d += warpsPerGrid) {
        int beg = g_off[d];
        int cnt = g_cnt[d];
        float dd = g_dis[d];
        float4 acc = *(const float4*)(g_h + (size_t)d * NF + lane * 4);
        acc.x *= dd; acc.y *= dd; acc.z *= dd; acc.w *= dd;

        int j = 0;
        for (; j + 8 <= cnt; j += 8) {
            int s[8];
#pragma unroll
            for (int u = 0; u < 8; u++) s[u] = g_src[beg + j + u];
            float wt[8];
#pragma unroll
            for (int u = 0; u < 8; u++) wt[u] = g_dis[s[u]];
            float4 v[8];
#pragma unroll
            for (int u = 0; u < 8; u++)
                v[u] = *(const float4*)(g_h + (size_t)s[u] * NF + lane * 4);
#pragma unroll
            for (int u = 0; u < 8; u++) {
                acc.x += wt[u] * v[u].x; acc.y += wt[u] * v[u].y;
                acc.z += wt[u] * v[u].z; acc.w += wt[u] * v[u].w;
            }
        }
        for (; j < cnt; j++) {
            int s = g_src[beg + j];
            float ww = g_dis[s];
            float4 v = *(const float4*)(g_h + (size_t)s * NF + lane * 4);
            acc.x += ww * v.x; acc.y += ww * v.y; acc.z += ww * v.z; acc.w += ww * v.w;
        }

        float4 o = make_float4(acc.x * dd + bv.x, acc.y * dd + bv.y,
                               acc.z * dd + bv.z, acc.w * dd + bv.w);
        *(float4*)(g_agg + (size_t)d * NF + lane * 4) = o;

        ls.x += o.x; ls.y += o.y; ls.z += o.z; ls.w += o.w;
        lq.x += o.x * o.x; lq.y += o.y * o.y; lq.z += o.z * o.z; lq.w += o.w * o.w;
    }

    *(float4*)(ssum + w * 128 + lane * 4) = ls;
    *(float4*)(ssq + w * 128 + lane * 4) = lq;
    __syncthreads();

    if (threadIdx.x < 128) {
        int f = threadIdx.x;
        float s = 0.f, q = 0.f;
#pragma unroll
        for (int k = 0; k < 8; k++) { s += ssum[k * 128 + f]; q += ssq[k * 128 + f]; }
        atomicAdd(&g_sum[f], s);
        atomicAdd(&g_sumsq[f], q);
    }
}

// ---- finalize stats ----
__global__ void k_fin(const float* __restrict__ gw, const float* __restrict__ gb,
                      const float* __restrict__ gms, float inv_n) {
    int f = threadIdx.x;
    float mean = g_sum[f] * inv_n;
    float ex2 = g_sumsq[f] * inv_n;
    float c = mean * gms[f];
    float var = ex2 - 2.f * c * mean + c * c;
    float sc = rsqrtf(var + 1e-5f) * gw[f];
    g_shift[f] = c;
    g_scale[f] = sc;
    g_beta[f] = gb[f];
}

// ---- normalize + LeakyReLU + edge copy, single kernel ----
__global__ void k_out(const int* __restrict__ ei, float* __restrict__ out,
                      int n, int m2) {
    int i = blockIdx.x * blockDim.x + threadIdx.x;
    int nodeGroups = n * 32;
    if (i < nodeGroups) {
        int f4 = (i & 31) << 2;
        float4 v = *(const float4*)(g_agg + (size_t)i * 4);
        float4 o;
        o.x = (v.x - g_shift[f4 + 0]) * g_scale[f4 + 0] + g_beta[f4 + 0];
        o.y = (v.y - g_shift[f4 + 1]) * g_scale[f4 + 1] + g_beta[f4 + 1];
        o.z = (v.z - g_shift[f4 + 2]) * g_scale[f4 + 2] + g_beta[f4 + 2];
        o.w = (v.w - g_shift[f4 + 3]) * g_scale[f4 + 3] + g_beta[f4 + 3];
        o.x = o.x > 0.f ? o.x : 0.01f * o.x;
        o.y = o.y > 0.f ? o.y : 0.01f * o.y;
        o.z = o.z > 0.f ? o.z : 0.01f * o.z;
        o.w = o.w > 0.f ? o.w : 0.01f * o.w;
        *(float4*)(out + (size_t)i * 4) = o;
    } else {
        int g = i - nodeGroups;
        int base = g * 4;
        if (base < m2) {
            float* dst = out + (size_t)n * NF + base;
            if (base + 4 <= m2) {
                int4 e = *(const int4*)(ei + base);
                float4 o = make_float4((float)e.x, (float)e.y, (float)e.z, (float)e.w);
                *(float4*)dst = o;
            } else {
                for (int k = 0; base + k < m2; k++) dst[k] = (float)ei[base + k];
            }
        }
    }
}

extern "C" void kernel_launch(void* const* d_in, const int* in_sizes, int n_in,
                              void* d_out, int out_size) {
    const float* x = (const float*)d_in[0];
    const int* ei = (const int*)d_in[1];
    const float* W = (const float*)d_in[2];
    const float* b = (const float*)d_in[3];
    const float* gw = (const float*)d_in[4];
    const float* gb = (const float*)d_in[5];
    const float* gms = (const float*)d_in[6];

    int n = in_sizes[0] / NF;
    int E = in_sizes[1] / 2;
    float* out = (float*)d_out;

    int smem = (64 * 132 + 64 * 128) * 4;

    // one-time resources (host-side objects only; no device memory allocation)
    static cudaStream_t s2 = nullptr;
    static cudaEvent_t evFork = nullptr, evJoin = nullptr;
    if (!s2) {
        cudaStreamCreateWithFlags(&s2, cudaStreamNonBlocking);
        cudaEventCreateWithFlags(&evFork, cudaEventDisableTiming);
        cudaEventCreateWithFlags(&evJoin, cudaEventDisableTiming);
        cudaFuncSetAttribute(k_gemm, cudaFuncAttributeMaxDynamicSharedMemorySize, smem);
    }

    int init_n = (n > NF ? n : NF);
    int NB = (n + 255) / 256;

    // fork: GEMM on s2, edge preprocessing on the capture (default) stream
    cudaEventRecord(evFork, 0);
    cudaStreamWaitEvent(s2, evFork, 0);
    k_gemm<<<(n + 127) / 128, 256, smem, s2>>>(x, W, n);
    cudaEventRecord(evJoin, s2);

    k_init<<<(init_n + 255) / 256, 256>>>(n);
    k_deg<<<(E + 255) / 256, 256>>>(ei, E);
    k_scan_block<<<NB, 256>>>(n);
    k_scan_top<<<1, 1024>>>(NB);
    k_scan_add<<<NB, 256>>>(n);
    k_bucket<<<(E + 255) / 256, 256>>>(ei, E);

    // join: k_agg needs both chains
    cudaStreamWaitEvent(0, evJoin, 0);

    int aggBlocks = (n + 7) / 8;
    if (aggBlocks > 1184) aggBlocks = 1184;
    k_agg<<<aggBlocks, 256>>>(b, n);

    k_fin<<<1, 128>>>(gw, gb, gms, 1.0f / (float)n);

    long long extra = (long long)out_size - (long long)n * NF;
    int m2 = 0;
    if (extra > 0) {
        m2 = (int)(extra < (long long)in_sizes[1] ? extra : (long long)in_sizes[1]);
    }
    long long totalThreads = (long long)n * 32 + (m2 + 3) / 4;
    k_out<<<(int)((totalThreads + 255) / 256), 256>>>(ei, out, n, m2);
}

// round 6
// speedup vs baseline: 2.1841x; 1.1215x over previous
#include <cuda_runtime.h>
#include <cuda_fp16.h>

#define NF 128
#define MAXN 100000
#define MAXE 2000000

// ---- scratch (device globals: no allocation allowed) ----
__device__ int    g_cnt[MAXN];
__device__ int    g_off[MAXN];
__device__ int    g_fill[MAXN];
__device__ int    g_bsum[1024];
__device__ int    g_src[MAXE];
__device__ float  g_dis[MAXN];
__device__ __half g_h[(size_t)MAXN * NF];     // fp16 h: halves gather traffic
__device__ float  g_agg[(size_t)MAXN * NF];
__device__ float  g_sum[NF];
__device__ float  g_sumsq[NF];
__device__ float  g_shift[NF];
__device__ float  g_scale[NF];
__device__ float  g_beta[NF];

// ---- packed f32x2 FMA ----
__device__ __forceinline__ void fma_f32x2(unsigned long long& acc,
                                          unsigned long long a,
                                          unsigned long long b) {
    asm("fma.rn.f32x2 %0, %1, %2, %0;" : "+l"(acc) : "l"(a), "l"(b));
}
__device__ __forceinline__ unsigned long long dup_f32x2(float v) {
    unsigned long long r;
    unsigned int u = __float_as_uint(v);
    asm("mov.b64 %0, {%1, %1};" : "=l"(r) : "r"(u));
    return r;
}
__device__ __forceinline__ float2 unpack_f32x2(unsigned long long p) {
    unsigned int lo, hi;
    asm("mov.b64 {%0, %1}, %2;" : "=r"(lo), "=r"(hi) : "l"(p));
    return make_float2(__uint_as_float(lo), __uint_as_float(hi));
}

// ---- init ----
__global__ void k_init(int n) {
    int i = blockIdx.x * blockDim.x + threadIdx.x;
    if (i < NF) { g_sum[i] = 0.f; g_sumsq[i] = 0.f; }
    if (i < n) { g_cnt[i] = 0; g_fill[i] = 0; }
}

// ---- degree count over dst ----
__global__ void k_deg(const int* __restrict__ ei, int E) {
    int i = blockIdx.x * blockDim.x + threadIdx.x;
    if (i < E) atomicAdd(&g_cnt[ei[E + i]], 1);
}

// ---- prefix scan; stage 1 also emits dis = rsqrt(deg) ----
__global__ void k_scan_block(int n) {
    __shared__ int sm[256];
    int i = blockIdx.x * 256 + threadIdx.x;
    int v = (i < n) ? g_cnt[i] : 0;
    sm[threadIdx.x] = v; __syncthreads();
    for (int ofs = 1; ofs < 256; ofs <<= 1) {
        int x = (threadIdx.x >= ofs) ? sm[threadIdx.x - ofs] : 0;
        __syncthreads();
        sm[threadIdx.x] += x;
        __syncthreads();
    }
    if (i < n) {
        g_off[i] = sm[threadIdx.x] - v;
        g_dis[i] = rsqrtf((float)(v + 1));
    }
    if (threadIdx.x == 255) g_bsum[blockIdx.x] = sm[255];
}

__global__ void k_scan_top(int nb) {
    __shared__ int sm[1024];
    int t = threadIdx.x;
    int v = (t < nb) ? g_bsum[t] : 0;
    sm[t] = v; __syncthreads();
    for (int ofs = 1; ofs < 1024; ofs <<= 1) {
        int x = (t >= ofs) ? sm[t - ofs] : 0;
        __syncthreads();
        sm[t] += x;
        __syncthreads();
    }
    if (t < nb) g_bsum[t] = sm[t] - v;
}

__global__ void k_scan_add(int n) {
    int i = blockIdx.x * 256 + threadIdx.x;
    if (i < n) g_off[i] += g_bsum[blockIdx.x];
}

// ---- bucket edges by dst ----
__global__ void k_bucket(const int* __restrict__ ei, int E) {
    int i = blockIdx.x * blockDim.x + threadIdx.x;
    if (i < E) {
        int s = ei[i];
        int d = ei[E + i];
        int slot = g_off[d] + atomicAdd(&g_fill[d], 1);
        g_src[slot] = s;
    }
}

// ---- GEMM: h = x @ W, FFMA2 inner, fp16 epilogue ----
__global__ void __launch_bounds__(256) k_gemm(const float* __restrict__ x,
                                              const float* __restrict__ W, int n) {
    extern __shared__ float sm[];
    float* xs = sm;              // [64][132]
    float* ws = sm + 64 * 132;   // [64][128]
    int tid = threadIdx.x;
    int tx = tid & 15, ty = tid >> 4;
    int rowBase = blockIdx.x * 128;

    unsigned long long acc[8][4];
#pragma unroll
    for (int i = 0; i < 8; i++)
#pragma unroll
        for (int j = 0; j < 4; j++) acc[i][j] = 0ULL;

    for (int kc = 0; kc < 128; kc += 64) {
        for (int i = tid; i < 2048; i += 256) {
            int row = i >> 4;
            int k4 = (i & 15) << 2;
            float4 v = make_float4(0.f, 0.f, 0.f, 0.f);
            int gr = rowBase + row;
            if (gr < n) v = *(const float4*)(x + (size_t)gr * NF + kc + k4);
            xs[(k4 + 0) * 132 + row] = v.x;
            xs[(k4 + 1) * 132 + row] = v.y;
            xs[(k4 + 2) * 132 + row] = v.z;
            xs[(k4 + 3) * 132 + row] = v.w;
        }
        for (int i = tid; i < 2048; i += 256) {
            int k = i >> 5;
            int c4 = (i & 31) << 2;
            *(float4*)(ws + k * NF + c4) =
                *(const float4*)(W + (size_t)(kc + k) * NF + c4);
        }
        __syncthreads();

        for (int k = 0; k < 64; k++) {
            float4 a0 = *(float4*)(xs + k * 132 + ty * 8);
            float4 a1 = *(float4*)(xs + k * 132 + ty * 8 + 4);
            ulonglong2 B0 = *(ulonglong2*)(ws + k * NF + tx * 8);
            ulonglong2 B1 = *(ulonglong2*)(ws + k * NF + tx * 8 + 4);
            unsigned long long b2[4] = {B0.x, B0.y, B1.x, B1.y};
            unsigned long long a2[8];
            a2[0] = dup_f32x2(a0.x); a2[1] = dup_f32x2(a0.y);
            a2[2] = dup_f32x2(a0.z); a2[3] = dup_f32x2(a0.w);
            a2[4] = dup_f32x2(a1.x); a2[5] = dup_f32x2(a1.y);
            a2[6] = dup_f32x2(a1.z); a2[7] = dup_f32x2(a1.w);
#pragma unroll
            for (int i = 0; i < 8; i++)
#pragma unroll
                for (int j = 0; j < 4; j++) fma_f32x2(acc[i][j], a2[i], b2[j]);
        }
        __syncthreads();
    }

#pragma unroll
    for (int i = 0; i < 8; i++) {
        int gr = rowBase + ty * 8 + i;
        if (gr < n) {
            float2 c0 = unpack_f32x2(acc[i][0]);
            float2 c1 = unpack_f32x2(acc[i][1]);
            float2 c2 = unpack_f32x2(acc[i][2]);
            float2 c3 = unpack_f32x2(acc[i][3]);
            __half2 h0 = __float22half2_rn(c0);
            __half2 h1 = __float22half2_rn(c1);
            __half2 h2 = __float22half2_rn(c2);
            __half2 h3 = __float22half2_rn(c3);
            uint4 pk;
            pk.x = *(unsigned int*)&h0;
            pk.y = *(unsigned int*)&h1;
            pk.z = *(unsigned int*)&h2;
            pk.w = *(unsigned int*)&h3;
            *(uint4*)(g_h + (size_t)gr * NF + tx * 8) = pk;
        }
    }
}

// ---- CSR aggregate (fp16 gather, fp32 accumulate) + fused stats ----
__global__ void __launch_bounds__(256) k_agg(const float* __restrict__ b, int n) {
    __shared__ float ssum[8 * 128];
    __shared__ float ssq[8 * 128];
    int warpsPerGrid = gridDim.x * 8;
    int w = threadIdx.x >> 5;
    int lane = threadIdx.x & 31;
    float4 bv = *(const float4*)(b + lane * 4);

    float4 ls = make_float4(0.f, 0.f, 0.f, 0.f);
    float4 lq = make_float4(0.f, 0.f, 0.f, 0.f);

    for (int d = blockIdx.x * 8 + w; d < n; d += warpsPerGrid) {
        int beg = g_off[d];
        int cnt = g_cnt[d];
        float dd = g_dis[d];

        // self term
        uint2 hp = *(const uint2*)(g_h + (size_t)d * NF + lane * 4);
        float2 s0 = __half22float2(*(__half2*)&hp.x);
        float2 s1 = __half22float2(*(__half2*)&hp.y);
        float4 acc = make_float4(s0.x * dd, s0.y * dd, s1.x * dd, s1.y * dd);

        int j = 0;
        for (; j + 8 <= cnt; j += 8) {
            int s[8];
#pragma unroll
            for (int u = 0; u < 8; u++) s[u] = g_src[beg + j + u];
            float wt[8];
#pragma unroll
            for (int u = 0; u < 8; u++) wt[u] = g_dis[s[u]];
            uint2 v[8];
#pragma unroll
            for (int u = 0; u < 8; u++)
                v[u] = *(const uint2*)(g_h + (size_t)s[u] * NF + lane * 4);
#pragma unroll
            for (int u = 0; u < 8; u++) {
                float2 a = __half22float2(*(__half2*)&v[u].x);
                float2 c = __half22float2(*(__half2*)&v[u].y);
                acc.x += wt[u] * a.x; acc.y += wt[u] * a.y;
                acc.z += wt[u] * c.x; acc.w += wt[u] * c.y;
            }
        }
        for (; j < cnt; j++) {
            int s = g_src[beg + j];
            float ww = g_dis[s];
            uint2 vv = *(const uint2*)(g_h + (size_t)s * NF + lane * 4);
            float2 a = __half22float2(*(__half2*)&vv.x);
            float2 c = __half22float2(*(__half2*)&vv.y);
            acc.x += ww * a.x; acc.y += ww * a.y;
            acc.z += ww * c.x; acc.w += ww * c.y;
        }

        float4 o = make_float4(acc.x * dd + bv.x, acc.y * dd + bv.y,
                               acc.z * dd + bv.z, acc.w * dd + bv.w);
        *(float4*)(g_agg + (size_t)d * NF + lane * 4) = o;

        ls.x += o.x; ls.y += o.y; ls.z += o.z; ls.w += o.w;
        lq.x += o.x * o.x; lq.y += o.y * o.y; lq.z += o.z * o.z; lq.w += o.w * o.w;
    }

    *(float4*)(ssum + w * 128 + lane * 4) = ls;
    *(float4*)(ssq + w * 128 + lane * 4) = lq;
    __syncthreads();

    if (threadIdx.x < 128) {
        int f = threadIdx.x;
        float s = 0.f, q = 0.f;
#pragma unroll
        for (int k = 0; k < 8; k++) { s += ssum[k * 128 + f]; q += ssq[k * 128 + f]; }
        atomicAdd(&g_sum[f], s);
        atomicAdd(&g_sumsq[f], q);
    }
}

// ---- finalize stats ----
__global__ void k_fin(const float* __restrict__ gw, const float* __restrict__ gb,
                      const float* __restrict__ gms, float inv_n) {
    int f = threadIdx.x;
    float mean = g_sum[f] * inv_n;
    float ex2 = g_sumsq[f] * inv_n;
    float c = mean * gms[f];
    float var = ex2 - 2.f * c * mean + c * c;
    float sc = rsqrtf(var + 1e-5f) * gw[f];
    g_shift[f] = c;
    g_scale[f] = sc;
    g_beta[f] = gb[f];
}

// ---- normalize + LeakyReLU + edge copy ----
__global__ void k_out(const int* __restrict__ ei, float* __restrict__ out,
                      int n, int m2) {
    int i = blockIdx.x * blockDim.x + threadIdx.x;
    int nodeGroups = n * 32;
    if (i < nodeGroups) {
        int f4 = (i & 31) << 2;
        float4 v = *(const float4*)(g_agg + (size_t)i * 4);
        float4 o;
        o.x = (v.x - g_shift[f4 + 0]) * g_scale[f4 + 0] + g_beta[f4 + 0];
        o.y = (v.y - g_shift[f4 + 1]) * g_scale[f4 + 1] + g_beta[f4 + 1];
        o.z = (v.z - g_shift[f4 + 2]) * g_scale[f4 + 2] + g_beta[f4 + 2];
        o.w = (v.w - g_shift[f4 + 3]) * g_scale[f4 + 3] + g_beta[f4 + 3];
        o.x = o.x > 0.f ? o.x : 0.01f * o.x;
        o.y = o.y > 0.f ? o.y : 0.01f * o.y;
        o.z = o.z > 0.f ? o.z : 0.01f * o.z;
        o.w = o.w > 0.f ? o.w : 0.01f * o.w;
        *(float4*)(out + (size_t)i * 4) = o;
    } else {
        int g = i - nodeGroups;
        int base = g * 4;
        if (base < m2) {
            float* dst = out + (size_t)n * NF + base;
            if (base + 4 <= m2) {
                int4 e = *(const int4*)(ei + base);
                float4 o = make_float4((float)e.x, (float)e.y, (float)e.z, (float)e.w);
                *(float4*)dst = o;
            } else {
                for (int k = 0; base + k < m2; k++) dst[k] = (float)ei[base + k];
            }
        }
    }
}

extern "C" void kernel_launch(void* const* d_in, const int* in_sizes, int n_in,
                              void* d_out, int out_size) {
    const float* x = (const float*)d_in[0];
    const int* ei = (const int*)d_in[1];
    const float* W = (const float*)d_in[2];
    const float* b = (const float*)d_in[3];
    const float* gw = (const float*)d_in[4];
    const float* gb = (const float*)d_in[5];
    const float* gms = (const float*)d_in[6];

    int n = in_sizes[0] / NF;
    int E = in_sizes[1] / 2;
    float* out = (float*)d_out;

    int smem = (64 * 132 + 64 * 128) * 4;

    static cudaStream_t s2 = nullptr;
    static cudaEvent_t evFork = nullptr, evJoin = nullptr;
    if (!s2) {
        cudaStreamCreateWithFlags(&s2, cudaStreamNonBlocking);
        cudaEventCreateWithFlags(&evFork, cudaEventDisableTiming);
        cudaEventCreateWithFlags(&evJoin, cudaEventDisableTiming);
        cudaFuncSetAttribute(k_gemm, cudaFuncAttributeMaxDynamicSharedMemorySize, smem);
    }

    int init_n = (n > NF ? n : NF);
    int NB = (n + 255) / 256;

    cudaEventRecord(evFork, 0);
    cudaStreamWaitEvent(s2, evFork, 0);
    k_gemm<<<(n + 127) / 128, 256, smem, s2>>>(x, W, n);
    cudaEventRecord(evJoin, s2);

    k_init<<<(init_n + 255) / 256, 256>>>(n);
    k_deg<<<(E + 255) / 256, 256>>>(ei, E);
    k_scan_block<<<NB, 256>>>(n);
    k_scan_top<<<1, 1024>>>(NB);
    k_scan_add<<<NB, 256>>>(n);
    k_bucket<<<(E + 255) / 256, 256>>>(ei, E);

    cudaStreamWaitEvent(0, evJoin, 0);

    int aggBlocks = (n + 7) / 8;
    if (aggBlocks > 1184) aggBlocks = 1184;
    k_agg<<<aggBlocks, 256>>>(b, n);

    k_fin<<<1, 128>>>(gw, gb, gms, 1.0f / (float)n);

    long long extra = (long long)out_size - (long long)n * NF;
    int m2 = 0;
    if (extra > 0) {
        m2 = (int)(extra < (long long)in_sizes[1] ? extra : (long long)in_sizes[1]);
    }
    long long totalThreads = (long long)n * 32 + (m2 + 3) / 4;
    k_out<<<(int)((totalThreads + 255) / 256), 256>>>(ei, out, n, m2);
}